// round 4
// baseline (speedup 1.0000x reference)
#include <cuda_runtime.h>
#include <math.h>

#define BB 16384
#define CC 8192
#define RPB 256              // rows per histogram block
#define NBLK (BB / RPB)      // 64

// ---------------- device scratch (no runtime allocation) ----------------
__device__ int   d_first[CC];          // first occurrence row per label (BB if absent)
__device__ int   d_cnt[CC];            // count per label
__device__ int   d_hist[NBLK * CC];    // per-row-block label histograms (raw counts)
__device__ int   d_start[BB];          // exclusive scan of group sizes (keyed by first-occ row)
__device__ int   d_lab[BB];            // normalized int32 labels
__device__ int   d_flagblk[32];        // per-block "odd word nonzero" flags
__device__ float d_loss[BB];           // per-row loss
__device__ unsigned int d_ticket;      // last-block election for loss reduction

// ---------------- setup: init first/cnt + label-width detection ----------------
// 32 x 256 = 8192 threads (= CC = BB/2). int64 labels (LE) have every odd
// 32-bit word zero; int32 labels make some odd word nonzero w.h.p.
__global__ void k_setup(const int* __restrict__ words) {
    int i = blockIdx.x * 256 + threadIdx.x;      // 0..8191
    d_first[i] = BB;
    d_cnt[i] = 0;
    int odd = (words[2 * i + 1] != 0);
    int any = __syncthreads_or(odd);
    if (threadIdx.x == 0) d_flagblk[blockIdx.x] = any;
    if (i == 0) d_ticket = 0;
}

// ---------------- convert + count (shared-memory histogram) ----------------
__global__ void __launch_bounds__(256) k_count(const void* __restrict__ labels) {
    __shared__ unsigned int sh[CC];   // 32KB block histogram
    __shared__ int s_is64;
    const int t = threadIdx.x, b = blockIdx.x;

    if (t < 32) {
        int v = d_flagblk[t];
        unsigned m = __ballot_sync(0xffffffffu, v != 0);
        if (t == 0) s_is64 = (m == 0);           // no odd word nonzero -> int64
    }
#pragma unroll
    for (int k = t; k < CC; k += 256) sh[k] = 0u;
    __syncthreads();

    const int i = b * 256 + t;
    const int lab = s_is64 ? (int)((const long long*)labels)[i]
                           : ((const int*)labels)[i];
    d_lab[i] = lab;
    atomicMin(&d_first[lab], i);
    atomicAdd(&d_cnt[lab], 1);
    atomicAdd(&sh[lab], 1u);
    __syncthreads();

#pragma unroll
    for (int k = t; k < CC; k += 256) d_hist[b * CC + k] = (int)sh[k];
}

// ---------------- group-start scan (single block) ----------------
// d_start = exclusive scan of g[r] = (first[lab[r]]==r) ? cnt[lab[r]] : 0
__global__ void __launch_bounds__(1024) k_mid() {
    __shared__ int sums[1024];
    const int t = threadIdx.x;
    const int base = t * 16;
    int local[16];
    int acc = 0;
#pragma unroll
    for (int k = 0; k < 16; k++) {
        int r = base + k;
        int lab = d_lab[r];
        int gv = (d_first[lab] == r) ? d_cnt[lab] : 0;
        local[k] = acc;
        acc += gv;
    }
    sums[t] = acc;
    __syncthreads();
    for (int off = 1; off < 1024; off <<= 1) {
        int v = (t >= off) ? sums[t - off] : 0;
        __syncthreads();
        sums[t] += v;
        __syncthreads();
    }
    int offset = (t == 0) ? 0 : sums[t - 1];
#pragma unroll
    for (int k = 0; k < 16; k++) d_start[base + k] = offset + local[k];
}

// ---------------- main fused streaming kernel ----------------
// One block per source row. Computes its own permutation destination
// (parallel rank reduction), streams margin-edited row to the permuted
// destination, accumulates sum-of-exp, last block reduces the loss.
__global__ void __launch_bounds__(256) k_main(const float* __restrict__ logits,
                                              float* __restrict__ out,
                                              long long osz) {
    const int row = blockIdx.x;
    const int t = threadIdx.x;
    const int lab = d_lab[row];
    __shared__ float red[8];
    __shared__ int sred[8];
    __shared__ int s_dst;

    // ---- parallel destination computation ----
    {
        const int blk = row >> 8, off = row & 255;
        int labj = d_lab[blk * 256 + t];
        int c = (t < off && labj == lab) ? 1 : 0;          // rank within block
        if (t < blk) c += d_hist[t * CC + lab];            // earlier blocks (t<blk<=63)
        // block int-sum
#pragma unroll
        for (int o = 16; o; o >>= 1) c += __shfl_xor_sync(0xffffffffu, c, o);
        if ((t & 31) == 0) sred[t >> 5] = c;
        __syncthreads();
        if (t == 0) {
            int r = sred[0] + sred[1] + sred[2] + sred[3]
                  + sred[4] + sred[5] + sred[6] + sred[7];
            s_dst = d_start[d_first[lab]] + r;
        }
        __syncthreads();
    }
    const int dst = s_dst;

    const float4* __restrict__ src = (const float4*)(logits + (size_t)row * CC);
    float4* __restrict__ o4 = (float4*)(out + (size_t)dst * CC);

    const int tgt4 = lab >> 2, tsub = lab & 3;
    const long long nbig = (long long)BB * CC;
    const bool do_store = (osz >= nbig);

    float s0 = 0.0f, s1 = 0.0f;
    float tval = 0.0f;
    bool have_t = false;

#pragma unroll
    for (int k = 0; k < 8; k++) {
        const int idx = k * 256 + t;
        float4 x = __ldcs(src + idx);
        if (idx == tgt4) {
            float vv = (tsub == 0) ? x.x : (tsub == 1) ? x.y : (tsub == 2) ? x.z : x.w;
            float nv = (vv > 0.0f) ? (vv / 2.00001f - 0.2f) : (vv * 2.00001f - 0.2f);
            if (tsub == 0) x.x = nv; else if (tsub == 1) x.y = nv;
            else if (tsub == 2) x.z = nv; else x.w = nv;
            tval = nv; have_t = true;
        }
        if (do_store) __stcs(o4 + idx, x);
        s0 += __expf(x.x) + __expf(x.y);
        s1 += __expf(x.z) + __expf(x.w);
    }

    // block float-sum reduction
    float ws = s0 + s1;
#pragma unroll
    for (int o = 16; o; o >>= 1) ws += __shfl_xor_sync(0xffffffffu, ws, o);
    if ((t & 31) == 0) red[t >> 5] = ws;
    __syncthreads();
    if (t < 32) {
        float x = (t < 8) ? red[t] : 0.0f;
#pragma unroll
        for (int o = 4; o; o >>= 1) x += __shfl_xor_sync(0xffffffffu, x, o);
        if (t == 0) red[0] = x;
    }
    __syncthreads();
    const float s = red[0];

    if (have_t) {
        d_loss[row] = __logf(s) - tval;
        __threadfence();                       // publish loss before ticket
    }
    if (t == 0 && osz >= nbig + BB) out[(size_t)nbig + dst] = (float)lab;

    // ---- last block performs the deterministic loss reduction ----
    __shared__ unsigned int s_last;
    __syncthreads();
    if (t == 0) s_last = atomicAdd(&d_ticket, 1u);
    __syncthreads();
    if (s_last == BB - 1) {
        __threadfence();
        __shared__ double sd[256];
        double a = 0.0;
        for (int i = t; i < BB; i += 256) a += (double)d_loss[i];
        sd[t] = a;
        __syncthreads();
        for (int o = 128; o; o >>= 1) {
            if (t < o) sd[t] += sd[t + o];
            __syncthreads();
        }
        if (t == 0) {
            float L = (float)(sd[0] / (double)BB);
            if (osz >= nbig + BB + 1)      out[(size_t)nbig + BB] = L;
            else if (osz == 1)             out[0] = L;
        }
    }
}

// ---------------- launch ----------------
extern "C" void kernel_launch(void* const* d_in, const int* in_sizes, int n_in,
                              void* d_out, int out_size) {
    const float* logits = (const float*)d_in[0];
    const void*  labels = d_in[1];
    float* out = (float*)d_out;
    long long osz = (long long)out_size;

    k_setup<<<32, 256>>>((const int*)labels);
    k_count<<<NBLK, RPB>>>(labels);
    k_mid<<<1, 1024>>>();
    k_main<<<BB, 256>>>(logits, out, osz);
}